// round 6
// baseline (speedup 1.0000x reference)
#include <cuda_runtime.h>

// Uniform cubic B-spline, convert-free evaluation.
// t = (x+1)*31.5 in [0,63). Magic-add rounds t to NEAREST int k; v = t-k in
// [-0.5,0.5). Two cubic pieces per knot k:
//   entry[2k+1] (v>=0): monomial coeffs of interval k   -> value p_k(v)
//   entry[2k+0] (v< 0): interval k-1 shifted by +1      -> value p_{k-1}(1+v)
// Classification is exact for every v, no boundary cases.
// Monomial coeffs per interval j from coeffs c[j..j+3]:
//   p0=(c0+4c1+c2)/6, p1=(c2-c0)/2, p2=(c0-2c1+c2)/2, p3=(c3-c0+3(c1-c2))/6
// Shift by +1: q0=p0+p1+p2+p3, q1=p1+2p2+3p3, q2=p2+3p3, q3=p3.
// Shared table replicated 8x across the eight 16B bank groups: every LDS.128
// quarter-warp phase is conflict-free for random indices.

#define REP   8
#define NIDX  128                 // 2 * 64 knots
#define MAGIC 12582912.0f         // 1.5 * 2^23

__device__ float4 g_tbl[NIDX];    // canonical (unreplicated) table

__device__ __forceinline__ float4 monomial(const float* __restrict__ c, int j) {
    float c0 = c[j], c1 = c[j + 1], c2 = c[j + 2], c3 = c[j + 3];
    float4 p;
    p.x = fmaf(4.0f, c1, c0 + c2) * 0.16666666666666666f;
    p.y = (c2 - c0) * 0.5f;
    p.z = fmaf(-2.0f, c1, c0 + c2) * 0.5f;
    p.w = fmaf(3.0f, c1 - c2, c3 - c0) * 0.16666666666666666f;
    return p;
}

__device__ __forceinline__ float4 shift1(float4 p) {   // q(v) = p(1+v)
    float4 q;
    q.x = p.x + p.y + p.z + p.w;
    q.y = fmaf(3.0f, p.w, fmaf(2.0f, p.z, p.y));
    q.z = fmaf(3.0f, p.w, p.z);
    q.w = p.w;
    return q;
}

__global__ void build_table(const float* __restrict__ coeffs) {
    int idx = threadIdx.x;        // 0..127
    if (idx >= NIDX) return;
    int k  = idx >> 1;
    int hi = idx & 1;             // 1: v>=0 piece, 0: v<0 piece
    float4 q;
    if (hi) {
        q = (k <= 62) ? monomial(coeffs, k) : shift1(monomial(coeffs, 62));
    } else {
        q = (k == 0) ? monomial(coeffs, 0) : shift1(monomial(coeffs, k - 1));
    }
    g_tbl[idx] = q;
}

__device__ __forceinline__ float eval_one(float x, const float4* __restrict__ tp) {
    float t  = fmaf(x, 31.5f, 31.5f);
    float r  = __fadd_rn(t, MAGIC);
    float kf = __fadd_rn(r, -MAGIC);           // round-to-nearest(t), exact
    float v  = t - kf;                         // in [-0.5, 0.5), exact
    int bits = __float_as_int(r);
    int vneg = ((unsigned)__float_as_int(v)) >> 31;
    int idx  = ((bits & 63) << 1) + 1 - vneg;  // 2k+1 (v>=0) or 2k (v<0)
    float4 p = tp[idx * REP];                  // tp pre-offset by bank-group
    return fmaf(fmaf(fmaf(p.w, v, p.z), v, p.y), v, p.x);
}

__device__ __forceinline__ float4 eval_four(float4 xv, const float4* __restrict__ tp) {
    float4 ov;
    ov.x = eval_one(xv.x, tp);
    ov.y = eval_one(xv.y, tp);
    ov.z = eval_one(xv.z, tp);
    ov.w = eval_one(xv.w, tp);
    return ov;
}

__global__ void __launch_bounds__(256, 8)
bspline_kernel(const float4* __restrict__ x4,
               float4* __restrict__ o4, int n4) {
    __shared__ float4 tbl[NIDX * REP];
    int tid = threadIdx.x;
    if (tid < NIDX) {
        float4 p = g_tbl[tid];                 // coalesced 2KB
        #pragma unroll
        for (int r = 0; r < REP; r++) {
            // rotate replica slot by thread id -> conflict-free STS.128
            tbl[tid * REP + ((r + tid) & (REP - 1))] = p;
        }
    }
    __syncthreads();

    const float4* __restrict__ tp = tbl + (tid & (REP - 1));
    const int stride = gridDim.x * blockDim.x;
    int i = blockIdx.x * blockDim.x + tid;

    for (; i + stride < n4; i += 2 * stride) {
        float4 xa = x4[i];
        float4 xb = x4[i + stride];
        o4[i]          = eval_four(xa, tp);
        o4[i + stride] = eval_four(xb, tp);
    }
    if (i < n4) {
        float4 xa = x4[i];
        o4[i] = eval_four(xa, tp);
    }
}

extern "C" void kernel_launch(void* const* d_in, const int* in_sizes, int n_in,
                              void* d_out, int out_size) {
    const float* x      = (const float*)d_in[0];
    const float* coeffs = (const float*)d_in[1];
    float* out = (float*)d_out;
    int n  = in_sizes[0];
    int n4 = n >> 2;                 // N = 2^22, divisible by 4
    build_table<<<1, NIDX>>>(coeffs);
    int threads = 256;
    int blocks  = 1184;              // 8 CTAs/SM x 148 SMs, one wave
    int max_blocks = (n4 + threads - 1) / threads;
    if (blocks > max_blocks) blocks = max_blocks;
    if (blocks < 1) blocks = 1;
    bspline_kernel<<<blocks, threads>>>((const float4*)x, (float4*)out, n4);
}